// round 15
// baseline (speedup 1.0000x reference)
#include <cuda_runtime.h>

#define NB 16
#define NH 592                    // hist-role blocks
#define NL 592                    // loss-role blocks
#define NBLK (NH + NL)            // 1184 = 148 SMs * 8 -> all co-resident
#define HWPIX (768*768)
#define NUM_IDS 128
#define NVEC (HWPIX/4)            // 147456 int4 per batch

// ---- scratch (allocation-free __device__ globals). g_cnt zero at load and
// re-zeroed by loss tails each run; flags/tickets/acc reset by consumers. ----
__device__ int   g_cnt [NB * NUM_IDS];
__device__ int   g_ni  [NB];
__device__ int   g_nbg [NB];
__device__ float g_acc [NB * 4];       // fgS, fgC, bgS, bgC per batch
__device__ int   g_flag[NB];           // hist(b) done -> 1; loss tail -> 0
__device__ int   g_tixh[NB];
__device__ int   g_tixl[NB];
__device__ int   g_fin;

__global__ void __launch_bounds__(256, 8)
k_all(const float* __restrict__ pred,
      const int*   __restrict__ inst,
      const float* __restrict__ gt,
      float*       __restrict__ out) {
    const int tid  = threadIdx.x;
    const int warp = tid >> 5;
    const int lane = tid & 31;
    const int bid  = blockIdx.x;

    __shared__ int   sh[8][NUM_IDS];   // hist per-warp tables (4KB)
    __shared__ float s_inv[NUM_IDS];
    __shared__ float s_r[4][8];
    __shared__ int   s_wni[4];
    __shared__ int   s_last;

    if (bid < NH) {
        // ================= HIST role: batches in order, flag on done =======
        const int i0 = bid * 256 + tid;
        for (int b = 0; b < NB; b++) {
            #pragma unroll
            for (int w = 0; w < 4; w++) sh[warp][lane + 32 * w] = 0;
            __syncthreads();
            if (i0 < NVEC) {
                int4 v = ((const int4*)(inst + (size_t)b * HWPIX))[i0];
                atomicAdd(&sh[warp][v.x], 1);
                atomicAdd(&sh[warp][v.y], 1);
                atomicAdd(&sh[warp][v.z], 1);
                atomicAdd(&sh[warp][v.w], 1);
            }
            __syncthreads();
            if (tid < NUM_IDS) {
                int t = 0;
                #pragma unroll
                for (int w = 0; w < 8; w++) t += sh[w][tid];
                if (t) atomicAdd(&g_cnt[b * NUM_IDS + tid], t);
            }
            if (tid == 0) {
                __threadfence();
                s_last = (atomicAdd(&g_tixh[b], 1) == NH - 1);
            }
            __syncthreads();
            if (s_last) {
                __threadfence();
                if (tid < NUM_IDS) {
                    int c = g_cnt[b * NUM_IDS + tid];
                    unsigned ball = __ballot_sync(0xFFFFFFFFu, tid > 0 && c > 0);
                    if (lane == 0) s_wni[warp] = __popc(ball);
                    if (tid == 0) g_nbg[b] = c;
                }
                __syncthreads();
                if (tid == 0) {
                    g_ni[b]   = s_wni[0] + s_wni[1] + s_wni[2] + s_wni[3];
                    g_tixh[b] = 0;
                    __threadfence();
                    atomicExch(&g_flag[b], 1);
                }
            }
            __syncthreads();
        }
    } else {
        // ================= LOSS role: lag hist by ~1 batch =================
        const int i0 = (bid - NH) * 256 + tid;
        for (int b = 0; b < NB; b++) {
            if (tid == 0) {
                while (atomicAdd(&g_flag[b], 0) == 0) __nanosleep(64);
            }
            __syncthreads();
            __threadfence();
            if (tid < NUM_IDS) {
                int c = g_cnt[b * NUM_IDS + tid];
                s_inv[tid] = (tid > 0 && c > 0) ? 1.0f / (float)c : 0.0f;
            }
            __syncthreads();

            float fgs = 0.0f, fgc = 0.0f, bgs = 0.0f, bgc = 0.0f;
            if (i0 < NVEC) {
                const float* pb = pred + (size_t)b * 2 * HWPIX;
                const float* gb = gt   + (size_t)b * 5 * HWPIX;
                int4   id = ((const int4*)(inst + (size_t)b * HWPIX))[i0];
                float4 s  = ((const float4*)pb)[i0];
                float4 c  = ((const float4*)(pb + HWPIX))[i0];
                float4 g1 = ((const float4*)(gb + 2 * (size_t)HWPIX))[i0];
                float4 g2 = ((const float4*)(gb + 3 * (size_t)HWPIX))[i0];
                float d;
                d = fabsf(s.x - g1.x); fgs += s_inv[id.x] * d; if (id.x == 0) bgs += d;
                d = fabsf(s.y - g1.y); fgs += s_inv[id.y] * d; if (id.y == 0) bgs += d;
                d = fabsf(s.z - g1.z); fgs += s_inv[id.z] * d; if (id.z == 0) bgs += d;
                d = fabsf(s.w - g1.w); fgs += s_inv[id.w] * d; if (id.w == 0) bgs += d;
                d = fabsf(c.x - g2.x); fgc += s_inv[id.x] * d; if (id.x == 0) bgc += d;
                d = fabsf(c.y - g2.y); fgc += s_inv[id.y] * d; if (id.y == 0) bgc += d;
                d = fabsf(c.z - g2.z); fgc += s_inv[id.z] * d; if (id.z == 0) bgc += d;
                d = fabsf(c.w - g2.w); fgc += s_inv[id.w] * d; if (id.w == 0) bgc += d;
            }
            // block-reduce the 4 accumulators
            for (int off = 16; off > 0; off >>= 1) {
                fgs += __shfl_down_sync(0xFFFFFFFFu, fgs, off);
                fgc += __shfl_down_sync(0xFFFFFFFFu, fgc, off);
                bgs += __shfl_down_sync(0xFFFFFFFFu, bgs, off);
                bgc += __shfl_down_sync(0xFFFFFFFFu, bgc, off);
            }
            if (lane == 0) {
                s_r[0][warp] = fgs; s_r[1][warp] = fgc;
                s_r[2][warp] = bgs; s_r[3][warp] = bgc;
            }
            __syncthreads();
            if (tid < 4) {
                float v = 0.0f;
                #pragma unroll
                for (int w = 0; w < 8; w++) v += s_r[tid][w];
                atomicAdd(&g_acc[b * 4 + tid], v);
            }
            if (tid == 0) {
                __threadfence();
                s_last = (atomicAdd(&g_tixl[b], 1) == NL - 1);
            }
            __syncthreads();
            if (s_last) {
                if (tid < NUM_IDS) g_cnt[b * NUM_IDS + tid] = 0;  // reset for next run
                if (tid == 0) {
                    g_tixl[b] = 0;
                    atomicExch(&g_flag[b], 0);
                    __threadfence();
                    s_last = (atomicAdd(&g_fin, 1) == NB - 1);
                }
                __syncthreads();
                if (s_last && tid == 0) {
                    __threadfence();
                    int ni = 0, nbg = 0;
                    #pragma unroll
                    for (int i = 0; i < NB; i++) { ni += g_ni[i]; nbg += g_nbg[i]; }
                    const float inv_ni = 1.0f / (2.0f * (float)ni);
                    const float inv_bg = 1.0f / (2.0f * (float)nbg);
                    #pragma unroll
                    for (int bb = 0; bb < NB; bb++) {
                        float ls = g_acc[bb * 4 + 0] * inv_ni + g_acc[bb * 4 + 2] * inv_bg;
                        float lc = g_acc[bb * 4 + 1] * inv_ni + g_acc[bb * 4 + 3] * inv_bg;
                        out[0 * NB + bb] = ls + lc;   // loss
                        out[1 * NB + bb] = ls + lc;   // loss_direction_total
                        out[2 * NB + bb] = 0.0f;      // loss_centers
                        out[3 * NB + bb] = ls;        // loss_sin
                        out[4 * NB + bb] = lc;        // loss_cos
                        g_acc[bb * 4 + 0] = 0.0f; g_acc[bb * 4 + 1] = 0.0f;
                        g_acc[bb * 4 + 2] = 0.0f; g_acc[bb * 4 + 3] = 0.0f;
                    }
                    g_fin = 0;
                }
            }
            __syncthreads();
        }
    }
}

extern "C" void kernel_launch(void* const* d_in, const int* in_sizes, int n_in,
                              void* d_out, int out_size) {
    const float* pred = (const float*)d_in[0];   // (16,2,768,768) f32
    const int*   inst = (const int*)d_in[1];     // (16,768,768) i32
    // d_in[2] = labels (unused: W_FG == W_BG == 1)
    const float* gt   = (const float*)d_in[3];   // (16,5,768,768) f32
    float* out = (float*)d_out;                  // 80 f32

    k_all<<<NBLK, 256>>>(pred, inst, gt, out);
}

// round 16
// speedup vs baseline: 1.8185x; 1.8185x over previous
#include <cuda_runtime.h>

#define NB 16
#define GH 74                     // hist blocks per batch (74*16 = 1184 = 148*8)
#define GL 36                     // loss blocks per batch (36*16 = 576)
#define NLBLK (GL * NB)
#define HWPIX (768*768)
#define NUM_IDS 128
#define NV16 (HWPIX/16)           // 36864 16-pixel groups per batch

// ---- scratch (allocation-free __device__ globals). Plain stores fully
// overwritten each run; tickets self-reset. ----
__device__ unsigned char g_pack[(size_t)NB * HWPIX];  // ids packed to bytes
__device__ int   g_part [GH * NB * NUM_IDS];          // per-block partial hists
__device__ int   g_cnt  [NB * NUM_IDS];               // per-batch counts
__device__ int   g_ni   [NB];                         // per-batch #instances
__device__ int   g_nbg  [NB];                         // per-batch bg pixels
__device__ float g_ploss[NLBLK * 2];                  // per-block (sin,cos)
__device__ int   g_tixh [NB];                         // per-batch hist tickets
__device__ int   g_tix;                               // loss ticket

// ---------------------------------------------------------------------------
// K1: histogram partials + id byte-packing, with a parallel per-batch ticket
// tail producing g_cnt / g_ni / g_nbg. Per-WARP privatized tables. (R10 ver.)
// ---------------------------------------------------------------------------
__global__ void __launch_bounds__(256, 8) k_hist(const int* __restrict__ inst) {
    const int tid  = threadIdx.x;
    const int warp = tid >> 5;
    const int lane = tid & 31;
    const int b    = blockIdx.y;
    const int bx   = blockIdx.x;

    __shared__ int sh[8][NUM_IDS];
    #pragma unroll
    for (int w = 0; w < 4; w++) sh[warp][lane + 32 * w] = 0;
    __syncthreads();

    int* mt = sh[warp];
    const int4* pi = (const int4*)(inst + (size_t)b * HWPIX);
    uchar4*     pk = (uchar4*)(g_pack + (size_t)b * HWPIX);
    for (int i = bx * 256 + tid; i < HWPIX / 4; i += GH * 256) {
        int4 v = __ldcs(pi + i);
        pk[i] = make_uchar4((unsigned char)v.x, (unsigned char)v.y,
                            (unsigned char)v.z, (unsigned char)v.w);
        atomicAdd(&mt[v.x], 1);
        atomicAdd(&mt[v.y], 1);
        atomicAdd(&mt[v.z], 1);
        atomicAdd(&mt[v.w], 1);
    }
    __syncthreads();

    if (tid < NUM_IDS) {
        int tot = 0;
        #pragma unroll
        for (int w = 0; w < 8; w++) tot += sh[w][tid];
        g_part[(b * GH + bx) * NUM_IDS + tid] = tot;
    }

    // ---- per-batch ticket: last block of this batch reduces the partials ---
    __shared__ int s_last;
    if (tid == 0) {
        __threadfence();
        s_last = (atomicAdd(&g_tixh[b], 1) == GH - 1);
    }
    __syncthreads();
    if (!s_last) return;
    __threadfence();

    const int id = tid & 127;
    const int j  = tid >> 7;           // 0..1
    int tot = 0;
    #pragma unroll
    for (int x = j; x < GH; x += 2)
        tot += g_part[(b * GH + x) * NUM_IDS + id];

    __shared__ int sp[2][NUM_IDS];
    sp[j][id] = tot;
    __syncthreads();

    __shared__ int s_wni[4];
    if (j == 0) {                      // tid 0..127 = warps 0..3
        tot += sp[1][id];
        g_cnt[b * NUM_IDS + id] = tot;
        unsigned ball = __ballot_sync(0xFFFFFFFFu, id > 0 && tot > 0);
        if (lane == 0) s_wni[warp] = __popc(ball);
        if (id == 0) g_nbg[b] = tot;
    }
    __syncthreads();
    if (tid == 0) {
        g_ni[b]   = s_wni[0] + s_wni[1] + s_wni[2] + s_wni[3];
        g_tixh[b] = 0;                 // self-reset for next graph replay
    }
}

// ---------------------------------------------------------------------------
// K2: weighted-L1 stream, 16 pixels/thread/iter so EVERY load is 16B:
// 1x uint4 (16 ids) + 4x float4 from each of the 4 data streams.
// No __ldcs: the 9.4MB pack array was just written -> L2 hits.
// ---------------------------------------------------------------------------
__global__ void __launch_bounds__(256) k_loss(const float* __restrict__ pred,
                                              const float* __restrict__ gt,
                                              float*       __restrict__ out) {
    const int tid = threadIdx.x;
    const int b   = blockIdx.y;
    const int bx  = blockIdx.x;
    const int bid = b * GL + bx;

    __shared__ float s_inv[NUM_IDS];
    {
        int ni = 0, nbg = 0;
        #pragma unroll
        for (int i = 0; i < NB; i++) { ni += g_ni[i]; nbg += g_nbg[i]; }
        float inv_bg = 1.0f / (2.0f * (float)nbg);
        float two_ni = 2.0f * (float)ni;
        if (tid < NUM_IDS) {
            float c = (float)max(g_cnt[b * NUM_IDS + tid], 1);
            s_inv[tid] = (tid == 0) ? inv_bg : 1.0f / (c * two_ni);
        }
    }
    __syncthreads();

    const float4* ps = (const float4*)(pred + (size_t)b * 2 * HWPIX);
    const float4* pc = (const float4*)(pred + (size_t)b * 2 * HWPIX + HWPIX);
    const float4* gs = (const float4*)(gt + (size_t)b * 5 * HWPIX + 2 * (size_t)HWPIX);
    const float4* gc = (const float4*)(gt + (size_t)b * 5 * HWPIX + 3 * (size_t)HWPIX);
    const uint4*  pid = (const uint4*)(g_pack + (size_t)b * HWPIX);

    float asin_ = 0.0f, acos_ = 0.0f;
    for (int v = bx * 256 + tid; v < NV16; v += GL * 256) {
        uint4 wv = pid[v];                       // 16 packed ids
        const int base = v * 4;
        #pragma unroll
        for (int j = 0; j < 4; j++) {
            unsigned w = (j == 0) ? wv.x : (j == 1) ? wv.y : (j == 2) ? wv.z : wv.w;
            float4 s  = ps[base + j];
            float4 c  = pc[base + j];
            float4 g1 = gs[base + j];
            float4 g2 = gc[base + j];
            float w0 = s_inv[w & 0xFF];
            float w1 = s_inv[(w >> 8)  & 0xFF];
            float w2 = s_inv[(w >> 16) & 0xFF];
            float w3 = s_inv[w >> 24];
            asin_ += w0 * fabsf(s.x - g1.x) + w1 * fabsf(s.y - g1.y)
                   + w2 * fabsf(s.z - g1.z) + w3 * fabsf(s.w - g1.w);
            acos_ += w0 * fabsf(c.x - g2.x) + w1 * fabsf(c.y - g2.y)
                   + w2 * fabsf(c.z - g2.z) + w3 * fabsf(c.w - g2.w);
        }
    }

    // block reduce
    for (int off = 16; off > 0; off >>= 1) {
        asin_ += __shfl_down_sync(0xFFFFFFFFu, asin_, off);
        acos_ += __shfl_down_sync(0xFFFFFFFFu, acos_, off);
    }
    __shared__ float ws[8], wc[8];
    const int lane = tid & 31, warp = tid >> 5;
    if (lane == 0) { ws[warp] = asin_; wc[warp] = acos_; }
    __syncthreads();
    if (tid == 0) {
        float vs = 0.0f, vc = 0.0f;
        #pragma unroll
        for (int i = 0; i < 8; i++) { vs += ws[i]; vc += wc[i]; }
        g_ploss[bid * 2 + 0] = vs;
        g_ploss[bid * 2 + 1] = vc;
    }

    // global ticket: last block writes the 5x16 output tuple
    __shared__ int s_last;
    if (tid == 0) {
        __threadfence();
        s_last = (atomicAdd(&g_tix, 1) == NLBLK - 1);
    }
    __syncthreads();
    if (!s_last) return;
    __threadfence();

    for (int bb = warp; bb < NB; bb += 8) {      // warp w -> batches w, w+8
        float ss = 0.0f, cc = 0.0f;
        for (int x = lane; x < GL; x += 32) {
            ss += g_ploss[(bb * GL + x) * 2 + 0];
            cc += g_ploss[(bb * GL + x) * 2 + 1];
        }
        for (int off = 16; off > 0; off >>= 1) {
            ss += __shfl_down_sync(0xFFFFFFFFu, ss, off);
            cc += __shfl_down_sync(0xFFFFFFFFu, cc, off);
        }
        if (lane == 0) {
            float t = ss + cc;
            out[0 * NB + bb] = t;      // loss
            out[1 * NB + bb] = t;      // loss_direction_total
            out[2 * NB + bb] = 0.0f;   // loss_centers
            out[3 * NB + bb] = ss;     // loss_sin
            out[4 * NB + bb] = cc;     // loss_cos
        }
    }
    if (tid == 0) g_tix = 0;           // self-reset for next graph replay
}

extern "C" void kernel_launch(void* const* d_in, const int* in_sizes, int n_in,
                              void* d_out, int out_size) {
    const float* pred = (const float*)d_in[0];   // (16,2,768,768) f32
    const int*   inst = (const int*)d_in[1];     // (16,768,768) i32
    // d_in[2] = labels (unused: W_FG == W_BG == 1)
    const float* gt   = (const float*)d_in[3];   // (16,5,768,768) f32
    float* out = (float*)d_out;                  // 80 f32

    k_hist<<<dim3(GH, NB), 256>>>(inst);
    k_loss<<<dim3(GL, NB), 256>>>(pred, gt, out);
}